// round 11
// baseline (speedup 1.0000x reference)
#include <cuda_runtime.h>

namespace {

constexpr int BATCH   = 4;
constexpr int NIN     = 1024;
constexpr int NOUT    = 1024;
constexpr int CH      = 8;     // density + 7 raw channels
constexpr int OC      = 16;
constexpr int OPB     = 32;    // outputs per block (= warp width)
constexpr int SPLITS  = 8;     // i-dimension splits across blocks
constexpr int ISPB    = NIN / SPLITS;      // 128 i per block
constexpr int THREADS = 256;
constexpr int WARPS   = THREADS / 32;      // 8
constexpr int IPW     = ISPB / WARPS;      // 16 i per warp

// Partial aggregates: [b*1024+O][split][c]  (1 MB scratch)
__device__ float g_part[BATCH * NOUT * SPLITS * CH];
// Per-otile completion counters (zero-init; finisher resets -> replay-safe)
__device__ int   g_count[BATCH * 32];

__device__ __forceinline__ float ex2_approx(float x) {
    float y;
    asm("ex2.approx.f32 %0, %1;" : "=f"(y) : "f"(x));
    return y;
}

// Packed dual-FMA: acc.{lo,hi} += y.{lo,hi} * m.{lo,hi}
__device__ __forceinline__ void ffma2(unsigned long long& acc,
                                      unsigned long long y,
                                      unsigned long long m) {
    asm("fma.rn.f32x2 %0, %1, %2, %0;" : "+l"(acc) : "l"(y), "l"(m));
}

__device__ __forceinline__ unsigned long long pack2(float w) {
    unsigned long long r;
    asm("mov.b64 %0, {%1, %1};" : "=l"(r) : "f"(w));
    return r;
}

__device__ __forceinline__ float2 unpack2(unsigned long long v) {
    float2 f;
    asm("mov.b64 {%0, %1}, %2;" : "=f"(f.x), "=f"(f.y) : "l"(v));
    return f;
}

// --------- Fused kernel: partial aggregation + last-block finish ---------
// (256, 5): 48-reg budget (R10-validated, no spills)
__global__ __launch_bounds__(THREADS, 5)
void convdeepset_kernel(const float* __restrict__ cx,     // [B, NIN, 1]
                        const float* __restrict__ cy,     // [B, NIN, 7]
                        const float* __restrict__ t,      // [B, NOUT, 1]
                        const float* __restrict__ sigma,  // [8]
                        const float* __restrict__ W,      // [8, 16]
                        const float* __restrict__ bias,   // [16]
                        float* __restrict__ out)          // [B*NOUT, 16]
{
    // sy[i] = [y1..y7, 1.0] -> two LDS.128 give 4 natural f32x2 pairs
    __shared__ float  sy[ISPB][CH];              // 4 KB
    __shared__ float  sx[ISPB];                  // 0.5 KB (pre-scaled x)
    __shared__ float  spart[WARPS][OPB][CH];     // 8 KB
    __shared__ float  sbeta[CH];
    __shared__ float  sagg2[OPB][CH];            // 1 KB (finisher only)
    __shared__ int    s_last;

    const int bi    = blockIdx.x;
    const int b     = bi >> 8;                   // / (32*8)
    const int otile = (bi >> 3) & 31;
    const int split = bi & 7;
    const int tid   = threadIdx.x;
    const int warp  = tid >> 5;
    const int lane  = tid & 31;
    const int i0    = split * ISPB;

    if (tid < CH) {
        float s = expf(sigma[tid]);
        sbeta[tid] = -0.5f * 1.4426950408889634f / (s * s);
    }

    // k = sqrt(-beta0): every thread computes (beta0 < 0 always)
    float s0 = expf(sigma[0]);
    const float kscale = sqrtf(0.5f * 1.4426950408889634f) / s0;

    // Stage y channels with density=1.0 in slot 7 (4 iters/thread)
    #pragma unroll
    for (int r = 0; r < 4; r++) {
        int idx = tid + r * THREADS;             // 0..1023
        int i = idx >> 3, c = idx & 7;
        sy[i][c] = (c < 7) ? cy[(b * NIN + i0 + i) * 7 + c] : 1.0f;
    }
    // Stage pre-scaled x
    if (tid < ISPB) sx[tid] = kscale * cx[b * NIN + i0 + tid];

    const float t_k = kscale * t[b * NOUT + otile * OPB + lane];
    __syncthreads();

    const float beta0 = sbeta[0];
    bool uni = true;
    #pragma unroll
    for (int c = 1; c < CH; c++) uni &= (sbeta[c] == beta0);

    // Canonical per-channel results: [den, y1..y7]
    float r_can[CH];

    const float4*    xw4 = reinterpret_cast<const float4*>(&sx[warp * IPW]);
    const longlong2* yw  = reinterpret_cast<const longlong2*>(&sy[warp * IPW][0]);

    if (uni) {
        unsigned long long a12 = 0, a34 = 0, a56 = 0, a7d = 0;
        #pragma unroll
        for (int jc = 0; jc < IPW / 4; jc++) {
            float4 x4 = xw4[jc];                 // 4 x values, one LDS.128
            #pragma unroll
            for (int u = 0; u < 4; u++) {
                int j = jc * 4 + u;
                float x = (u == 0) ? x4.x : (u == 1) ? x4.y
                        : (u == 2) ? x4.z : x4.w;
                float d = x - t_k;               // scaled distance
                float w = ex2_approx(-(d * d));  // exp2(beta0 * d2)
                longlong2 p0 = yw[2 * j];        // {y1,y2},{y3,y4} (broadcast)
                longlong2 p1 = yw[2 * j + 1];    // {y5,y6},{y7,1}
                unsigned long long ww = pack2(w);
                ffma2(a12, (unsigned long long)p0.x, ww);
                ffma2(a34, (unsigned long long)p0.y, ww);
                ffma2(a56, (unsigned long long)p1.x, ww);
                ffma2(a7d, (unsigned long long)p1.y, ww);
            }
        }
        float2 u12 = unpack2(a12), u34 = unpack2(a34);
        float2 u56 = unpack2(a56), u7d = unpack2(a7d);
        r_can[0] = u7d.y;                        // density
        r_can[1] = u12.x; r_can[2] = u12.y;
        r_can[3] = u34.x; r_can[4] = u34.y;
        r_can[5] = u56.x; r_can[6] = u56.y;
        r_can[7] = u7d.x;
    } else {
        // ratios: a_c = (beta_c/beta0) * a, where a = beta0*d2
        float ratio[CH];
        #pragma unroll
        for (int c = 0; c < CH; c++) ratio[c] = sbeta[c] / beta0;
        float acc[CH];
        #pragma unroll
        for (int c = 0; c < CH; c++) acc[c] = 0.0f;
        const float* yws = &sy[warp * IPW][0];
        const float* xw  = &sx[warp * IPW];
        #pragma unroll 2
        for (int j = 0; j < IPW; j++) {
            float d = xw[j] - t_k;
            float a = -(d * d);                  // = beta0 * d2
            acc[0] += ex2_approx(ratio[0] * a);               // density
            #pragma unroll
            for (int c = 1; c < CH; c++)
                acc[c] += yws[j * CH + (c - 1)] * ex2_approx(ratio[c] * a);
        }
        #pragma unroll
        for (int c = 0; c < CH; c++) r_can[c] = acc[c];
    }

    // Per-warp partials (canonical order)
    *reinterpret_cast<float4*>(&spart[warp][lane][0]) =
        make_float4(r_can[0], r_can[1], r_can[2], r_can[3]);
    *reinterpret_cast<float4*>(&spart[warp][lane][4]) =
        make_float4(r_can[4], r_can[5], r_can[6], r_can[7]);
    __syncthreads();

    // Cross-warp reduce: one thread per (o, c); write partial to scratch
    const int G0 = b * NOUT + otile * OPB;
    {
        int o = tid >> 3, c = tid & 7;
        float s = 0.0f;
        #pragma unroll
        for (int w2 = 0; w2 < WARPS; w2++) s += spart[w2][o][c];
        g_part[((G0 + o) * SPLITS + split) * CH + c] = s;
    }

    // ---- last-block-done gate (threadFenceReduction pattern) ----
    __threadfence();
    if (tid == 0) {
        int old = atomicAdd(&g_count[b * 32 + otile], 1);
        s_last = (old == SPLITS - 1);
        if (s_last) g_count[b * 32 + otile] = 0;   // reset for next replay
    }
    __syncthreads();
    if (!s_last) return;

    // ---- finish: combine splits + normalize (one thread per (o, c)) ----
    {
        int o = tid >> 3, c = tid & 7;               // 32 x 8 = 256 threads
        const float* p = &g_part[((G0 + o) * SPLITS) * CH + c];
        float s = 0.0f;
        #pragma unroll
        for (int sp = 0; sp < SPLITS; sp++) s += p[sp * CH];
        float den = __shfl_sync(0xffffffffu, s, lane & ~7u);
        sagg2[o][c] = (c == 0) ? s : s / (den + 1e-8f);
    }
    __syncthreads();

    // ---- finish: out[G][k] = bias[k] + sum_c agg2[c] * W[c][k] ----
    #pragma unroll
    for (int r = 0; r < 2; r++) {
        int idx = tid + r * THREADS;                 // 0..511
        int o = idx >> 4, k = idx & 15;
        float v = __ldg(&bias[k]);
        #pragma unroll
        for (int c = 0; c < CH; c++) v += sagg2[o][c] * __ldg(&W[c * OC + k]);
        out[(G0 + o) * OC + k] = v;                  // coalesced
    }
}

} // namespace

extern "C" void kernel_launch(void* const* d_in, const int* in_sizes, int n_in,
                              void* d_out, int out_size) {
    const float* cx = (const float*)d_in[0];  // context_x
    const float* cy = (const float*)d_in[1];  // context_y
    const float* t  = (const float*)d_in[2];  // t
    const float* sg = (const float*)d_in[3];  // sigma
    const float* W  = (const float*)d_in[4];  // W
    const float* bi = (const float*)d_in[5];  // b
    float* out = (float*)d_out;

    convdeepset_kernel<<<BATCH * 32 * SPLITS, THREADS>>>(cx, cy, t, sg, W, bi, out);
}

// round 12
// speedup vs baseline: 1.0599x; 1.0599x over previous
#include <cuda_runtime.h>

namespace {

constexpr int BATCH   = 4;
constexpr int NIN     = 1024;
constexpr int NOUT    = 1024;
constexpr int CH      = 8;     // density + 7 raw channels
constexpr int OC      = 16;
constexpr int OPB     = 32;    // outputs per block (= warp width)
constexpr int SPLITS  = 4;     // i-dimension splits across blocks
constexpr int ISPB    = NIN / SPLITS;      // 256 i per block
constexpr int THREADS = 256;
constexpr int WARPS   = THREADS / 32;      // 8
constexpr int IPW     = ISPB / WARPS;      // 32 i per warp

// Partial aggregates: [b*1024+O][split][c]  (512 KB scratch)
__device__ float g_part[BATCH * NOUT * SPLITS * CH];
// Per-otile completion counters (zero-init; finisher resets -> replay-safe)
__device__ int   g_count[BATCH * 32];

__device__ __forceinline__ float ex2_approx(float x) {
    float y;
    asm("ex2.approx.f32 %0, %1;" : "=f"(y) : "f"(x));
    return y;
}

// --------- Fused kernel: partial aggregation + last-block finish ---------
// (256, 5): 48-reg budget (R10-validated, no spills)
__global__ __launch_bounds__(THREADS, 5)
void convdeepset_kernel(const float* __restrict__ cx,     // [B, NIN, 1]
                        const float* __restrict__ cy,     // [B, NIN, 7]
                        const float* __restrict__ t,      // [B, NOUT, 1]
                        const float* __restrict__ sigma,  // [8]
                        const float* __restrict__ W,      // [8, 16]
                        const float* __restrict__ bias,   // [16]
                        float* __restrict__ out)          // [B*NOUT, 16]
{
    // sy[i] = [y1,y2,y3,y4],[y5,y6,y7,1.0] -> two broadcast LDS.128
    __shared__ float  sy[ISPB][CH];              // 8 KB
    __shared__ float  sx[ISPB];                  // 1 KB (pre-scaled x)
    __shared__ float  spart[WARPS][OPB][CH];     // 8 KB
    __shared__ float  sbeta[CH];
    __shared__ float  sagg2[OPB][CH];            // 1 KB (finisher only)
    __shared__ int    s_last;

    const int bi    = blockIdx.x;
    const int b     = bi >> 7;                   // / (32*4)
    const int otile = (bi >> 2) & 31;
    const int split = bi & 3;
    const int tid   = threadIdx.x;
    const int warp  = tid >> 5;
    const int lane  = tid & 31;
    const int i0    = split * ISPB;

    if (tid < CH) {
        float s = expf(sigma[tid]);
        sbeta[tid] = -0.5f * 1.4426950408889634f / (s * s);
    }

    // k = sqrt(-beta0): every thread computes (beta0 < 0 always)
    float s0 = expf(sigma[0]);
    const float kscale = sqrtf(0.5f * 1.4426950408889634f) / s0;

    // Stage y channels with density=1.0 in slot 7
    #pragma unroll
    for (int r = 0; r < 8; r++) {
        int idx = tid + r * THREADS;             // 0..2047
        int i = idx >> 3, c = idx & 7;
        sy[i][c] = (c < 7) ? cy[(b * NIN + i0 + i) * 7 + c] : 1.0f;
    }
    // Stage pre-scaled x (256 threads, 1 element each)
    sx[tid] = kscale * cx[b * NIN + i0 + tid];

    const float t_k = kscale * t[b * NOUT + otile * OPB + lane];
    __syncthreads();

    const float beta0 = sbeta[0];
    bool uni = true;
    #pragma unroll
    for (int c = 1; c < CH; c++) uni &= (sbeta[c] == beta0);

    // Accumulators in y-slot order: [y1..y7, den]
    float acc[CH];
    #pragma unroll
    for (int c = 0; c < CH; c++) acc[c] = 0.0f;

    const float4* xw4 = reinterpret_cast<const float4*>(&sx[warp * IPW]);
    const float4* yw  = reinterpret_cast<const float4*>(&sy[warp * IPW][0]);

    if (uni) {
        #pragma unroll
        for (int jc = 0; jc < IPW / 4; jc++) {
            float4 x4 = xw4[jc];                 // 4 x values, one LDS.128
            #pragma unroll
            for (int u = 0; u < 4; u++) {
                int j = jc * 4 + u;
                float x = (u == 0) ? x4.x : (u == 1) ? x4.y
                        : (u == 2) ? x4.z : x4.w;
                float d = x - t_k;               // scaled distance
                float w = ex2_approx(-(d * d));  // exp2(beta0 * d2)
                float4 p0 = yw[2 * j];           // {y1,y2,y3,y4} (broadcast)
                float4 p1 = yw[2 * j + 1];       // {y5,y6,y7,1}
                acc[0] += p0.x * w;  acc[1] += p0.y * w;
                acc[2] += p0.z * w;  acc[3] += p0.w * w;
                acc[4] += p1.x * w;  acc[5] += p1.y * w;
                acc[6] += p1.z * w;  acc[7] += w;        // density: y==1
            }
        }
    } else {
        // ratios: a_c = (beta_c/beta0) * a, where a = beta0*d2
        float ratio[CH];
        #pragma unroll
        for (int c = 0; c < CH; c++) ratio[c] = sbeta[c] / beta0;
        const float* yws = &sy[warp * IPW][0];
        const float* xw  = &sx[warp * IPW];
        #pragma unroll 2
        for (int j = 0; j < IPW; j++) {
            float d = xw[j] - t_k;
            float a = -(d * d);                  // = beta0 * d2
            #pragma unroll
            for (int c = 0; c < 7; c++)
                acc[c] += yws[j * CH + c] * ex2_approx(ratio[c + 1] * a);
            acc[7] += ex2_approx(ratio[0] * a);  // density
        }
    }

    // Per-warp partials in canonical order [den, y1..y7]
    *reinterpret_cast<float4*>(&spart[warp][lane][0]) =
        make_float4(acc[7], acc[0], acc[1], acc[2]);
    *reinterpret_cast<float4*>(&spart[warp][lane][4]) =
        make_float4(acc[3], acc[4], acc[5], acc[6]);
    __syncthreads();

    // Cross-warp reduce: one thread per (o, c); write partial to scratch
    const int G0 = b * NOUT + otile * OPB;
    {
        int o = tid >> 3, c = tid & 7;
        float s = 0.0f;
        #pragma unroll
        for (int w2 = 0; w2 < WARPS; w2++) s += spart[w2][o][c];
        g_part[((G0 + o) * SPLITS + split) * CH + c] = s;
    }

    // ---- last-block-done gate (threadFenceReduction pattern) ----
    __threadfence();
    if (tid == 0) {
        int old = atomicAdd(&g_count[b * 32 + otile], 1);
        s_last = (old == SPLITS - 1);
        if (s_last) g_count[b * 32 + otile] = 0;   // reset for next replay
    }
    __syncthreads();
    if (!s_last) return;

    // ---- finish: combine splits + normalize (one thread per (o, c)) ----
    {
        int o = tid >> 3, c = tid & 7;               // 32 x 8 = 256 threads
        const float* p = &g_part[((G0 + o) * SPLITS) * CH + c];
        float s = 0.0f;
        #pragma unroll
        for (int sp = 0; sp < SPLITS; sp++) s += p[sp * CH];
        float den = __shfl_sync(0xffffffffu, s, lane & ~7u);
        sagg2[o][c] = (c == 0) ? s : s / (den + 1e-8f);
    }
    __syncthreads();

    // ---- finish: out[G][k] = bias[k] + sum_c agg2[c] * W[c][k] ----
    #pragma unroll
    for (int r = 0; r < 2; r++) {
        int idx = tid + r * THREADS;                 // 0..511
        int o = idx >> 4, k = idx & 15;
        float v = __ldg(&bias[k]);
        #pragma unroll
        for (int c = 0; c < CH; c++) v += sagg2[o][c] * __ldg(&W[c * OC + k]);
        out[(G0 + o) * OC + k] = v;                  // coalesced
    }
}

} // namespace

extern "C" void kernel_launch(void* const* d_in, const int* in_sizes, int n_in,
                              void* d_out, int out_size) {
    const float* cx = (const float*)d_in[0];  // context_x
    const float* cy = (const float*)d_in[1];  // context_y
    const float* t  = (const float*)d_in[2];  // t
    const float* sg = (const float*)d_in[3];  // sigma
    const float* W  = (const float*)d_in[4];  // W
    const float* bi = (const float*)d_in[5];  // b
    float* out = (float*)d_out;

    convdeepset_kernel<<<BATCH * 32 * SPLITS, THREADS>>>(cx, cy, t, sg, W, bi, out);
}

// round 13
// speedup vs baseline: 1.1831x; 1.1163x over previous
#include <cuda_runtime.h>

namespace {

constexpr int BATCH   = 4;
constexpr int NIN     = 1024;
constexpr int NOUT    = 1024;
constexpr int CH      = 8;     // density + 7 raw channels
constexpr int OC      = 16;
constexpr int OPB     = 32;    // outputs per block (= warp width)
constexpr int SPLITS  = 4;     // i-dimension splits across blocks
constexpr int ISPB    = NIN / SPLITS;      // 256 i per block
constexpr int THREADS = 256;
constexpr int WARPS   = THREADS / 32;      // 8
constexpr int IPW     = ISPB / WARPS;      // 32 i per warp

// Partial aggregates: [b*1024+O][split][c]  (512 KB scratch)
__device__ float g_part[BATCH * NOUT * SPLITS * CH];
// Per-otile completion counters (zero-init; finisher resets -> replay-safe)
__device__ int   g_count[BATCH * 32];

__device__ __forceinline__ float ex2_approx(float x) {
    float y;
    asm("ex2.approx.f32 %0, %1;" : "=f"(y) : "f"(x));
    return y;
}

// Packed dual-FMA: acc.{lo,hi} += y.{lo,hi} * m.{lo,hi}
__device__ __forceinline__ void ffma2(unsigned long long& acc,
                                      unsigned long long y,
                                      unsigned long long m) {
    asm("fma.rn.f32x2 %0, %1, %2, %0;" : "+l"(acc) : "l"(y), "l"(m));
}

__device__ __forceinline__ unsigned long long pack2(float w) {
    unsigned long long r;
    asm("mov.b64 %0, {%1, %1};" : "=l"(r) : "f"(w));
    return r;
}

__device__ __forceinline__ float2 unpack2(unsigned long long v) {
    float2 f;
    asm("mov.b64 {%0, %1}, %2;" : "=f"(f.x), "=f"(f.y) : "l"(v));
    return f;
}

// --------- Fused kernel: partial aggregation + last-block finish ---------
// (256, 4): 64-reg budget; occupancy is grid-limited anyway (512 blocks)
__global__ __launch_bounds__(THREADS, 4)
void convdeepset_kernel(const float* __restrict__ cx,     // [B, NIN, 1]
                        const float* __restrict__ cy,     // [B, NIN, 7]
                        const float* __restrict__ t,      // [B, NOUT, 1]
                        const float* __restrict__ sigma,  // [8]
                        const float* __restrict__ W,      // [8, 16]
                        const float* __restrict__ bias,   // [16]
                        float* __restrict__ out)          // [B*NOUT, 16]
{
    // sy[i] = [y1..y7, 1.0] -> two LDS.128 give 4 natural f32x2 pairs
    __shared__ float  sy[ISPB][CH];              // 8 KB
    __shared__ float  sx[ISPB];                  // 1 KB (pre-scaled x)
    __shared__ float  spart[WARPS][OPB][CH];     // 8 KB
    __shared__ float  sbeta[CH];
    __shared__ float  sagg2[OPB][CH];            // 1 KB (finisher only)
    __shared__ int    s_last;

    const int bi    = blockIdx.x;
    const int b     = bi >> 7;                   // / (32*4)
    const int otile = (bi >> 2) & 31;
    const int split = bi & 3;
    const int tid   = threadIdx.x;
    const int warp  = tid >> 5;
    const int lane  = tid & 31;
    const int i0    = split * ISPB;

    if (tid < CH) {
        float s = expf(sigma[tid]);
        sbeta[tid] = -0.5f * 1.4426950408889634f / (s * s);
    }

    // k = sqrt(-beta0): every thread computes (beta0 < 0 always)
    float s0 = expf(sigma[0]);
    const float kscale = sqrtf(0.5f * 1.4426950408889634f) / s0;

    // Stage y channels with density=1.0 in slot 7
    #pragma unroll
    for (int r = 0; r < 8; r++) {
        int idx = tid + r * THREADS;             // 0..2047
        int i = idx >> 3, c = idx & 7;
        sy[i][c] = (c < 7) ? cy[(b * NIN + i0 + i) * 7 + c] : 1.0f;
    }
    // Stage pre-scaled x (256 threads, 1 element each)
    sx[tid] = kscale * cx[b * NIN + i0 + tid];

    const float t_k = kscale * t[b * NOUT + otile * OPB + lane];
    __syncthreads();

    const float beta0 = sbeta[0];
    bool uni = true;
    #pragma unroll
    for (int c = 1; c < CH; c++) uni &= (sbeta[c] == beta0);

    // Canonical per-channel results: [den, y1..y7]
    float r_can[CH];

    const float4*    xw4 = reinterpret_cast<const float4*>(&sx[warp * IPW]);
    const longlong2* yw  = reinterpret_cast<const longlong2*>(&sy[warp * IPW][0]);

    if (uni) {
        unsigned long long a12 = 0, a34 = 0, a56 = 0, a7d = 0;
        #pragma unroll
        for (int jc = 0; jc < IPW / 4; jc++) {
            // --- 4 independent exp chains: MUFUs pipeline at rt=8 ---
            float4 x4 = xw4[jc];                 // one LDS.128
            float d0 = x4.x - t_k;
            float d1 = x4.y - t_k;
            float d2 = x4.z - t_k;
            float d3 = x4.w - t_k;
            float w0 = ex2_approx(-(d0 * d0));
            float w1 = ex2_approx(-(d1 * d1));
            float w2 = ex2_approx(-(d2 * d2));
            float w3 = ex2_approx(-(d3 * d3));
            unsigned long long ww0 = pack2(w0);
            unsigned long long ww1 = pack2(w1);
            unsigned long long ww2 = pack2(w2);
            unsigned long long ww3 = pack2(w3);
            // --- 8 broadcast y loads + 16 FFMA2 against ready w's ---
            longlong2 q0 = yw[8 * jc + 0];
            longlong2 q1 = yw[8 * jc + 1];
            longlong2 q2 = yw[8 * jc + 2];
            longlong2 q3 = yw[8 * jc + 3];
            longlong2 q4 = yw[8 * jc + 4];
            longlong2 q5 = yw[8 * jc + 5];
            longlong2 q6 = yw[8 * jc + 6];
            longlong2 q7 = yw[8 * jc + 7];
            ffma2(a12, (unsigned long long)q0.x, ww0);
            ffma2(a34, (unsigned long long)q0.y, ww0);
            ffma2(a56, (unsigned long long)q1.x, ww0);
            ffma2(a7d, (unsigned long long)q1.y, ww0);
            ffma2(a12, (unsigned long long)q2.x, ww1);
            ffma2(a34, (unsigned long long)q2.y, ww1);
            ffma2(a56, (unsigned long long)q3.x, ww1);
            ffma2(a7d, (unsigned long long)q3.y, ww1);
            ffma2(a12, (unsigned long long)q4.x, ww2);
            ffma2(a34, (unsigned long long)q4.y, ww2);
            ffma2(a56, (unsigned long long)q5.x, ww2);
            ffma2(a7d, (unsigned long long)q5.y, ww2);
            ffma2(a12, (unsigned long long)q6.x, ww3);
            ffma2(a34, (unsigned long long)q6.y, ww3);
            ffma2(a56, (unsigned long long)q7.x, ww3);
            ffma2(a7d, (unsigned long long)q7.y, ww3);
        }
        float2 u12 = unpack2(a12), u34 = unpack2(a34);
        float2 u56 = unpack2(a56), u7d = unpack2(a7d);
        r_can[0] = u7d.y;                        // density
        r_can[1] = u12.x; r_can[2] = u12.y;
        r_can[3] = u34.x; r_can[4] = u34.y;
        r_can[5] = u56.x; r_can[6] = u56.y;
        r_can[7] = u7d.x;
    } else {
        // ratios: a_c = (beta_c/beta0) * a, where a = beta0*d2
        float ratio[CH];
        #pragma unroll
        for (int c = 0; c < CH; c++) ratio[c] = sbeta[c] / beta0;
        float acc[CH];
        #pragma unroll
        for (int c = 0; c < CH; c++) acc[c] = 0.0f;
        const float* yws = &sy[warp * IPW][0];
        const float* xw  = &sx[warp * IPW];
        #pragma unroll 2
        for (int j = 0; j < IPW; j++) {
            float d = xw[j] - t_k;
            float a = -(d * d);                  // = beta0 * d2
            acc[0] += ex2_approx(ratio[0] * a);               // density
            #pragma unroll
            for (int c = 1; c < CH; c++)
                acc[c] += yws[j * CH + (c - 1)] * ex2_approx(ratio[c] * a);
        }
        #pragma unroll
        for (int c = 0; c < CH; c++) r_can[c] = acc[c];
    }

    // Per-warp partials (canonical order)
    *reinterpret_cast<float4*>(&spart[warp][lane][0]) =
        make_float4(r_can[0], r_can[1], r_can[2], r_can[3]);
    *reinterpret_cast<float4*>(&spart[warp][lane][4]) =
        make_float4(r_can[4], r_can[5], r_can[6], r_can[7]);
    __syncthreads();

    // Cross-warp reduce: one thread per (o, c); write partial to scratch
    const int G0 = b * NOUT + otile * OPB;
    {
        int o = tid >> 3, c = tid & 7;
        float s = 0.0f;
        #pragma unroll
        for (int w2 = 0; w2 < WARPS; w2++) s += spart[w2][o][c];
        g_part[((G0 + o) * SPLITS + split) * CH + c] = s;
    }

    // ---- last-block-done gate (threadFenceReduction pattern) ----
    __threadfence();
    if (tid == 0) {
        int old = atomicAdd(&g_count[b * 32 + otile], 1);
        s_last = (old == SPLITS - 1);
        if (s_last) g_count[b * 32 + otile] = 0;   // reset for next replay
    }
    __syncthreads();
    if (!s_last) return;

    // ---- finish: combine splits + normalize (one thread per (o, c)) ----
    {
        int o = tid >> 3, c = tid & 7;               // 32 x 8 = 256 threads
        const float* p = &g_part[((G0 + o) * SPLITS) * CH + c];
        float s = 0.0f;
        #pragma unroll
        for (int sp = 0; sp < SPLITS; sp++) s += p[sp * CH];
        float den = __shfl_sync(0xffffffffu, s, lane & ~7u);
        sagg2[o][c] = (c == 0) ? s : s / (den + 1e-8f);
    }
    __syncthreads();

    // ---- finish: out[G][k] = bias[k] + sum_c agg2[c] * W[c][k] ----
    #pragma unroll
    for (int r = 0; r < 2; r++) {
        int idx = tid + r * THREADS;                 // 0..511
        int o = idx >> 4, k = idx & 15;
        float v = __ldg(&bias[k]);
        #pragma unroll
        for (int c = 0; c < CH; c++) v += sagg2[o][c] * __ldg(&W[c * OC + k]);
        out[(G0 + o) * OC + k] = v;                  // coalesced
    }
}

} // namespace

extern "C" void kernel_launch(void* const* d_in, const int* in_sizes, int n_in,
                              void* d_out, int out_size) {
    const float* cx = (const float*)d_in[0];  // context_x
    const float* cy = (const float*)d_in[1];  // context_y
    const float* t  = (const float*)d_in[2];  // t
    const float* sg = (const float*)d_in[3];  // sigma
    const float* W  = (const float*)d_in[4];  // W
    const float* bi = (const float*)d_in[5];  // b
    float* out = (float*)d_out;

    convdeepset_kernel<<<BATCH * 32 * SPLITS, THREADS>>>(cx, cy, t, sg, W, bi, out);
}